// round 14
// baseline (speedup 1.0000x reference)
#include <cuda_runtime.h>
#include <cstdint>

#define NB    4096      // batch rows
#define NE    1024      // embed dim
#define NF    32768     // features
#define KTOP  64
#define KDEAD 512
#define CUT_DEAD 50000

// ================= scratch (static device globals; no allocations) =================
__device__ float    sc_proj[(size_t)NB * NF];     // chain fp32 projections (ref-family order)
__device__ float    sc_cons[(size_t)NB * NF];     // consensus fp32 = RN(exact sum)
__device__ float    sc_embm[(size_t)NB * NE];     // embed - bias
__device__ int      sc_tidx[NB * KTOP];
__device__ float    sc_twgt[NB * KTOP];
__device__ int      sc_didx[NB * KDEAD];
__device__ float    sc_dwgt[NB * KDEAD];
__device__ unsigned sc_mask[NF / 32];

typedef unsigned long long u64t;

__device__ __forceinline__ u64t pack_ff(float a, float b) {
    u64t r; asm("mov.b64 %0, {%1,%2};" : "=l"(r) : "f"(a), "f"(b)); return r;
}
__device__ __forceinline__ void unpack_ff(u64t v, float& lo, float& hi) {
    asm("mov.b64 {%0,%1}, %2;" : "=f"(lo), "=f"(hi) : "l"(v));
}
__device__ __forceinline__ void dfma(u64t& c, u64t a, u64t b) {
    asm("fma.rn.f32x2 %0, %1, %2, %0;" : "+l"(c) : "l"(a), "l"(b));
}
__device__ __forceinline__ u64t padd(u64t a, u64t b) {
    u64t r; asm("add.rn.f32x2 %0, %1, %2;" : "=l"(r) : "l"(a), "l"(b)); return r;
}
__device__ __forceinline__ u64t pneg(u64t a) {           // exact per-lane negation
    return a ^ 0x8000000080000000ull;
}
__device__ __forceinline__ u64t psub(u64t a, u64t b) { return padd(a, pneg(b)); }

// Packed exact TwoSum accumulate: (s,e) += p, per 32-bit lane, all IEEE RN.
__device__ __forceinline__ void p2sum(u64t& s, u64t p, u64t& e) {
    u64t t  = padd(s, p);
    u64t bb = psub(t, s);
    u64t t1 = psub(t, bb);
    u64t d1 = psub(s, t1);
    u64t d2 = psub(p, bb);
    e = padd(e, padd(d1, d2));
    s = t;
}

// ================= stage 1: embm = embed - bias =================
__global__ void ae_sub_bias(const float* __restrict__ embed,
                            const float* __restrict__ bias) {
    int i = blockIdx.x * blockDim.x + threadIdx.x;    // float4 index
    if (i < NB * NE / 4) {
        float4 e = ((const float4*)embed)[i];
        float4 b = ((const float4*)bias)[i & (NE / 4 - 1)];
        e.x -= b.x; e.y -= b.y; e.z -= b.z; e.w -= b.w;
        ((float4*)sc_embm)[i] = e;
    }
}

// ================= stage 2: dead mask (int32/int64 autodetect) =================
__global__ __launch_bounds__(1024)
void ae_build_mask(const int* __restrict__ lu) {
    __shared__ int s_hi_nonzero;
    const int t = threadIdx.x;
    if (t == 0) s_hi_nonzero = 0;
    __syncthreads();
    int nz = 0;
    for (int f = t; f < NF / 2; f += 1024) nz += (lu[2 * f + 1] != 0);
    if (nz) atomicAdd(&s_hi_nonzero, 1);
    __syncthreads();
    const bool is64 = (s_hi_nonzero == 0);
    unsigned m = 0;
    #pragma unroll
    for (int j = 0; j < 32; ++j) {
        int f = t * 32 + j;
        int v = is64 ? lu[2 * f] : lu[f];
        if (v > CUT_DEAD) m |= (1u << j);
    }
    sc_mask[t] = m;
}

// ================= stage 3a: chain GEMM (proven bit-family of the reference) =================
#define TBM 128
#define TBN 128
#define TBK 16
#define LDT 132

__global__ __launch_bounds__(128, 2)
void ae_project(const float* __restrict__ W) {
    __shared__ float sA[TBK * LDT];
    __shared__ float sB[TBK * LDT];

    const int t  = threadIdx.x;
    const int tn = t & 15;
    const int tm = t >> 4;
    const int m0 = blockIdx.x * TBM;
    const int n0 = blockIdx.y * TBN;

    const int lr = t >> 2;
    const int lc = (t & 3) * 4;

    const float* Ab = sc_embm + (size_t)(m0 + lr) * NE + lc;
    const float* Bb = W       + (size_t)(n0 + lr) * NE + lc;

    u64t acc[4][2][2][4];
    #pragma unroll
    for (int i = 0; i < 4; ++i)
        #pragma unroll
        for (int p = 0; p < 2; ++p)
            #pragma unroll
            for (int j = 0; j < 2; ++j)
                #pragma unroll
                for (int q = 0; q < 4; ++q) acc[i][p][j][q] = 0ull;

    float4 ra[4], rb[4];
    #pragma unroll
    for (int s = 0; s < 4; ++s) {
        ra[s] = *(const float4*)(Ab + (size_t)s * 32 * NE);
        rb[s] = *(const float4*)(Bb + (size_t)s * 32 * NE);
    }

    const int NSTEP = NE / TBK;     // 64
    for (int kt = 0; kt < NSTEP; ++kt) {
        #pragma unroll
        for (int s = 0; s < 4; ++s) {
            int r = lr + s * 32;
            sA[(lc + 0) * LDT + r] = ra[s].x;
            sA[(lc + 1) * LDT + r] = ra[s].y;
            sA[(lc + 2) * LDT + r] = ra[s].z;
            sA[(lc + 3) * LDT + r] = ra[s].w;
            sB[(lc + 0) * LDT + r] = rb[s].x;
            sB[(lc + 1) * LDT + r] = rb[s].y;
            sB[(lc + 2) * LDT + r] = rb[s].z;
            sB[(lc + 3) * LDT + r] = rb[s].w;
        }
        __syncthreads();

        if (kt + 1 < NSTEP) {
            const float* An = Ab + (kt + 1) * TBK;
            const float* Bn = Bb + (kt + 1) * TBK;
            #pragma unroll
            for (int s = 0; s < 4; ++s) {
                ra[s] = *(const float4*)(An + (size_t)s * 32 * NE);
                rb[s] = *(const float4*)(Bn + (size_t)s * 32 * NE);
            }
        }

        const float4* A4 = (const float4*)sA;
        const float4* B4 = (const float4*)sB;
        #pragma unroll
        for (int k = 0; k < TBK; ++k) {
            float4 av[4], bv[2];
            #pragma unroll
            for (int i = 0; i < 4; ++i) av[i] = A4[k * (LDT / 4) + tm + i * 8];
            bv[0] = B4[k * (LDT / 4) + tn];
            bv[1] = B4[k * (LDT / 4) + tn + 16];

            u64t am[4][2];
            #pragma unroll
            for (int i = 0; i < 4; ++i) {
                am[i][0] = pack_ff(av[i].x, av[i].y);
                am[i][1] = pack_ff(av[i].z, av[i].w);
            }
            u64t bd[2][4];
            #pragma unroll
            for (int j = 0; j < 2; ++j) {
                bd[j][0] = pack_ff(bv[j].x, bv[j].x);
                bd[j][1] = pack_ff(bv[j].y, bv[j].y);
                bd[j][2] = pack_ff(bv[j].z, bv[j].z);
                bd[j][3] = pack_ff(bv[j].w, bv[j].w);
            }
            #pragma unroll
            for (int i = 0; i < 4; ++i)
                #pragma unroll
                for (int p = 0; p < 2; ++p)
                    #pragma unroll
                    for (int j = 0; j < 2; ++j)
                        #pragma unroll
                        for (int q = 0; q < 4; ++q)
                            dfma(acc[i][p][j][q], am[i][p], bd[j][q]);
        }
        __syncthreads();
    }

    #pragma unroll
    for (int i = 0; i < 4; ++i)
        #pragma unroll
        for (int p = 0; p < 2; ++p) {
            float lo[8], hi[8];
            #pragma unroll
            for (int j = 0; j < 2; ++j)
                #pragma unroll
                for (int q = 0; q < 4; ++q)
                    unpack_ff(acc[i][p][j][q], lo[j * 4 + q], hi[j * 4 + q]);
            int mlo = m0 + tm * 4 + i * 32 + p * 2;
            float4* Cl = (float4*)(sc_proj + (size_t)mlo * NF + n0);
            float4* Ch = (float4*)(sc_proj + (size_t)(mlo + 1) * NF + n0);
            Cl[tn]      = make_float4(lo[0], lo[1], lo[2], lo[3]);
            Cl[tn + 16] = make_float4(lo[4], lo[5], lo[6], lo[7]);
            Ch[tn]      = make_float4(hi[0], hi[1], hi[2], hi[3]);
            Ch[tn + 16] = make_float4(hi[4], hi[5], hi[6], hi[7]);
        }
}

// ================= stage 3b: consensus GEMM  cons = RN(exact(embm @ W^T)) =================
// BM=128, BN=64, BK=16, 256 threads, 8(m) x 4(n) per thread.
// 4-step fp32 packed partials drained by packed exact TwoSum into (s,e);
// consensus = RN_fp32((double)s + (double)e). Residual error ~4e-8 << ulp/4.
#define CBM 128
#define CBN 64
#define CAS 132
#define CBS 68

__global__ __launch_bounds__(256)
void ae_consensus(const float* __restrict__ W) {
    __shared__ float sA[TBK * CAS];
    __shared__ float sB[TBK * CBS];

    const int t  = threadIdx.x;
    const int tn = t & 15;        // 16 n-threads * 4 = 64
    const int tm = t >> 4;        // 16 m-threads * 8 = 128
    const int m0 = blockIdx.x * CBM;
    const int n0 = blockIdx.y * CBN;

    const int ar0 = t >> 2,         ac0 = (t & 3) * 4;
    const int ar1 = (t + 256) >> 2, ac1 = ((t + 256) & 3) * 4;
    const int br  = t >> 2,         bc  = (t & 3) * 4;

    const float* Ab0 = sc_embm + (size_t)(m0 + ar0) * NE + ac0;
    const float* Ab1 = sc_embm + (size_t)(m0 + ar1) * NE + ac1;
    const float* Bb  = W       + (size_t)(n0 + br)  * NE + bc;

    u64t part[4][4], s[4][4], e[4][4];
    #pragma unroll
    for (int i = 0; i < 4; ++i)
        #pragma unroll
        for (int j = 0; j < 4; ++j) { part[i][j] = 0ull; s[i][j] = 0ull; e[i][j] = 0ull; }

    float4 pa0 = *(const float4*)Ab0;
    float4 pa1 = *(const float4*)Ab1;
    float4 pb  = *(const float4*)Bb;

    const int NSTEP = NE / TBK;     // 64
    for (int kt = 0; kt < NSTEP; ++kt) {
        __syncthreads();
        sA[(ac0 + 0) * CAS + ar0] = pa0.x;
        sA[(ac0 + 1) * CAS + ar0] = pa0.y;
        sA[(ac0 + 2) * CAS + ar0] = pa0.z;
        sA[(ac0 + 3) * CAS + ar0] = pa0.w;
        sA[(ac1 + 0) * CAS + ar1] = pa1.x;
        sA[(ac1 + 1) * CAS + ar1] = pa1.y;
        sA[(ac1 + 2) * CAS + ar1] = pa1.z;
        sA[(ac1 + 3) * CAS + ar1] = pa1.w;
        sB[(bc + 0) * CBS + br] = pb.x;
        sB[(bc + 1) * CBS + br] = pb.y;
        sB[(bc + 2) * CBS + br] = pb.z;
        sB[(bc + 3) * CBS + br] = pb.w;
        __syncthreads();

        if (kt + 1 < NSTEP) {
            int ko = (kt + 1) * TBK;
            pa0 = *(const float4*)(Ab0 + ko);
            pa1 = *(const float4*)(Ab1 + ko);
            pb  = *(const float4*)(Bb + ko);
        }

        const float4* A4 = (const float4*)sA;
        const float4* B4 = (const float4*)sB;
        #pragma unroll
        for (int kc = 0; kc < 4; ++kc) {
            #pragma unroll
            for (int k4 = 0; k4 < 4; ++k4) {
                int k = kc * 4 + k4;
                float4 a0 = A4[k * (CAS / 4) + tm * 2];
                float4 a1 = A4[k * (CAS / 4) + tm * 2 + 1];
                float4 b0 = B4[k * (CBS / 4) + tn];

                u64t am[4];
                am[0] = pack_ff(a0.x, a0.y); am[1] = pack_ff(a0.z, a0.w);
                am[2] = pack_ff(a1.x, a1.y); am[3] = pack_ff(a1.z, a1.w);
                u64t bd[4];
                bd[0] = pack_ff(b0.x, b0.x); bd[1] = pack_ff(b0.y, b0.y);
                bd[2] = pack_ff(b0.z, b0.z); bd[3] = pack_ff(b0.w, b0.w);

                #pragma unroll
                for (int i = 0; i < 4; ++i)
                    #pragma unroll
                    for (int j = 0; j < 4; ++j)
                        dfma(part[i][j], am[i], bd[j]);
            }
            // drain 4-step partial exactly into (s,e)
            #pragma unroll
            for (int i = 0; i < 4; ++i)
                #pragma unroll
                for (int j = 0; j < 4; ++j) {
                    p2sum(s[i][j], part[i][j], e[i][j]);
                    part[i][j] = 0ull;
                }
        }
    }

    #pragma unroll
    for (int i = 0; i < 4; ++i) {
        float slo[4], shi[4], elo[4], ehi[4];
        #pragma unroll
        for (int j = 0; j < 4; ++j) {
            unpack_ff(s[i][j], slo[j], shi[j]);
            unpack_ff(e[i][j], elo[j], ehi[j]);
        }
        int mlo = m0 + tm * 8 + 2 * i;
        float4 vlo = make_float4((float)((double)slo[0] + (double)elo[0]),
                                 (float)((double)slo[1] + (double)elo[1]),
                                 (float)((double)slo[2] + (double)elo[2]),
                                 (float)((double)slo[3] + (double)elo[3]));
        float4 vhi = make_float4((float)((double)shi[0] + (double)ehi[0]),
                                 (float)((double)shi[1] + (double)ehi[1]),
                                 (float)((double)shi[2] + (double)ehi[2]),
                                 (float)((double)shi[3] + (double)ehi[3]));
        *(float4*)(sc_cons + (size_t)mlo * NF + n0 + tn * 4)       = vlo;
        *(float4*)(sc_cons + (size_t)(mlo + 1) * NF + n0 + tn * 4) = vhi;
    }
}

// ================= stage 4: exact top-k, deterministic, HIGH-index ties =================
__device__ __forceinline__ unsigned mono_key(float f) {
    unsigned u = __float_as_uint(f);
    return (u & 0x80000000u) ? ~u : (u | 0x80000000u);
}
__device__ __forceinline__ float inv_key(unsigned k) {
    unsigned u = (k & 0x80000000u) ? (k & 0x7FFFFFFFu) : ~k;
    return __uint_as_float(u);
}

struct SelCtl {
    unsigned prefix;
    unsigned above;
    unsigned need;
    unsigned thr;
    int eq_total;
};

// which==0: main top-64 from sc_proj (no mask). which==1: dead top-512 from sc_cons (masked).
__global__ __launch_bounds__(256)
void ae_select(int which) {
    extern __shared__ unsigned dynsm[];
    unsigned* keys = dynsm;            // NF words
    unsigned* hist = dynsm + NF;       // 2048 words
    __shared__ unsigned s_m[NF / 32];
    __shared__ SelCtl sv;
    __shared__ int s_gcnt[256], s_ecnt[256];

    const int row = blockIdx.x;
    const int tid = threadIdx.x;
    const int NT = 256;

    const bool masked = (which == 1);
    const int K = masked ? KDEAD : KTOP;
    const float* src = masked ? (sc_cons + (size_t)row * NF)
                              : (sc_proj + (size_t)row * NF);
    int*   out_idx = masked ? (sc_didx + (size_t)row * KDEAD)
                            : (sc_tidx + (size_t)row * KTOP);
    float* out_w   = masked ? (sc_dwgt + (size_t)row * KDEAD)
                            : (sc_twgt + (size_t)row * KTOP);

    const float4* p4 = (const float4*)src;
    for (int i = tid; i < NF / 4; i += NT) {
        float4 v = p4[i];
        ((uint4*)keys)[i] = make_uint4(mono_key(v.x), mono_key(v.y),
                                       mono_key(v.z), mono_key(v.w));
    }
    for (int i = tid; i < NF / 32; i += NT) s_m[i] = sc_mask[i];
    if (tid == 0) { sv.need = (unsigned)K; sv.above = 0; }
    __syncthreads();

    // level 1: bits [31:21]
    for (int b = tid; b < 2048; b += NT) hist[b] = 0;
    __syncthreads();
    for (int i = tid; i < NF; i += NT) {
        if (masked && !((s_m[i >> 5] >> (i & 31)) & 1u)) continue;
        atomicAdd(&hist[keys[i] >> 21], 1u);
    }
    __syncthreads();
    if (tid == 0) {
        unsigned need = sv.need, cum = 0; int sel = 0;
        for (int b = 2047; b >= 0; --b) {
            unsigned c = hist[b];
            if (cum + c >= need) { sel = b; break; }
            cum += c;
        }
        sv.above += cum; sv.need = need - cum; sv.prefix = (unsigned)sel;
    }
    __syncthreads();
    const unsigned p1 = sv.prefix;

    // level 2: bits [20:10]
    for (int b = tid; b < 2048; b += NT) hist[b] = 0;
    __syncthreads();
    for (int i = tid; i < NF; i += NT) {
        if (masked && !((s_m[i >> 5] >> (i & 31)) & 1u)) continue;
        unsigned k = keys[i];
        if ((k >> 21) != p1) continue;
        atomicAdd(&hist[(k >> 10) & 2047u], 1u);
    }
    __syncthreads();
    if (tid == 0) {
        unsigned need = sv.need, cum = 0; int sel = 0;
        for (int b = 2047; b >= 0; --b) {
            unsigned c = hist[b];
            if (cum + c >= need) { sel = b; break; }
            cum += c;
        }
        sv.above += cum; sv.need = need - cum;
        sv.prefix = (p1 << 11) | (unsigned)sel;
    }
    __syncthreads();
    const unsigned p2 = sv.prefix;

    // level 3: bits [9:0]
    for (int b = tid; b < 1024; b += NT) hist[b] = 0;
    __syncthreads();
    for (int i = tid; i < NF; i += NT) {
        if (masked && !((s_m[i >> 5] >> (i & 31)) & 1u)) continue;
        unsigned k = keys[i];
        if ((k >> 10) != p2) continue;
        atomicAdd(&hist[k & 1023u], 1u);
    }
    __syncthreads();
    if (tid == 0) {
        unsigned need = sv.need, cum = 0; int sel = 0;
        for (int b = 1023; b >= 0; --b) {
            unsigned c = hist[b];
            if (cum + c >= need) { sel = b; break; }
            cum += c;
        }
        sv.above += cum; sv.need = need - cum;
        sv.thr = (p2 << 10) | (unsigned)sel;
        sv.eq_total = 0;
    }
    __syncthreads();

    const unsigned thr = sv.thr;
    const int above  = (int)sv.above;
    const int needEq = (int)sv.need;

    // deterministic collection: contiguous chunks, block prefix scan
    const int CHUNK = NF / NT;   // 128
    const int base = tid * CHUNK;
    int cgt = 0, ceq = 0;
    for (int i = base; i < base + CHUNK; ++i) {
        if (masked && !((s_m[i >> 5] >> (i & 31)) & 1u)) continue;
        unsigned k = keys[i];
        cgt += (k > thr);
        ceq += (k == thr);
    }
    s_gcnt[tid] = cgt;
    s_ecnt[tid] = ceq;
    __syncthreads();
    if (tid == 0) {
        int ag = 0, ae = 0;
        for (int j = 0; j < NT; ++j) {
            int g = s_gcnt[j], ec = s_ecnt[j];
            s_gcnt[j] = ag; s_ecnt[j] = ae;
            ag += g; ae += ec;
        }
        sv.eq_total = ae;
    }
    __syncthreads();

    // ties HIGH (proven R8/R9): keep the HIGHEST needEq indices in the bucket.
    const int eq_skip = sv.eq_total - needEq;

    int gpos = s_gcnt[tid];
    int epos = s_ecnt[tid];
    for (int i = base; i < base + CHUNK; ++i) {
        if (masked && !((s_m[i >> 5] >> (i & 31)) & 1u)) continue;
        unsigned k = keys[i];
        if (k > thr) {
            out_idx[gpos] = i;
            out_w[gpos]   = inv_key(k);
            ++gpos;
        } else if (k == thr) {
            int slot = epos - eq_skip;
            if (slot >= 0 && slot < needEq) {
                out_idx[above + slot] = i;
                out_w[above + slot]   = inv_key(k);
            }
            ++epos;
        }
    }
}

// ================= stage 5: reconstructions =================
__global__ __launch_bounds__(256)
void ae_recon_main(const float* __restrict__ lookup,
                   const float* __restrict__ bias,
                   float* __restrict__ out) {
    const int row = blockIdx.x;
    const int t = threadIdx.x;
    __shared__ int   si[KTOP];
    __shared__ float sw[KTOP];
    if (t < KTOP) {
        si[t] = sc_tidx[row * KTOP + t];
        sw[t] = sc_twgt[row * KTOP + t];
    }
    __syncthreads();
    float4 acc = ((const float4*)bias)[t];
    const float4* L4 = (const float4*)lookup;
    #pragma unroll 8
    for (int k = 0; k < KTOP; ++k) {
        float4 v = L4[(size_t)si[k] * (NE / 4) + t];
        float w = sw[k];
        acc.x = fmaf(w, v.x, acc.x);
        acc.y = fmaf(w, v.y, acc.y);
        acc.z = fmaf(w, v.z, acc.z);
        acc.w = fmaf(w, v.w, acc.w);
    }
    ((float4*)out)[(size_t)row * (NE / 4) + t] = acc;
}

__global__ __launch_bounds__(256)
void ae_recon_dead(const float* __restrict__ lookup,
                   float* __restrict__ out) {
    const int row = blockIdx.x;
    const int t = threadIdx.x;
    __shared__ int   si[KDEAD];
    __shared__ float sw[KDEAD];
    for (int k = t; k < KDEAD; k += 256) {
        si[k] = sc_didx[(size_t)row * KDEAD + k];
        sw[k] = sc_dwgt[(size_t)row * KDEAD + k];
    }
    __syncthreads();
    float4 acc = make_float4(0.f, 0.f, 0.f, 0.f);
    const float4* L4 = (const float4*)lookup;
    #pragma unroll 8
    for (int k = 0; k < KDEAD; ++k) {
        float4 v = L4[(size_t)si[k] * (NE / 4) + t];
        float w = sw[k];
        acc.x = fmaf(w, v.x, acc.x);
        acc.y = fmaf(w, v.y, acc.y);
        acc.z = fmaf(w, v.z, acc.z);
        acc.w = fmaf(w, v.w, acc.w);
    }
    ((float4*)out)[(size_t)row * (NE / 4) + t] = acc;
}

// ================= launcher =================
extern "C" void kernel_launch(void* const* d_in, const int* in_sizes, int n_in,
                              void* d_out, int out_size) {
    const float* embed      = (const float*)d_in[0];
    const float* enc_bias   = (const float*)d_in[1];
    const float* enc_W      = (const float*)d_in[2];
    const float* lookup     = (const float*)d_in[3];
    const int*   last_usage = (const int*)d_in[4];
    float* out = (float*)d_out;

    (void)in_sizes; (void)n_in; (void)out_size;

    ae_sub_bias<<<(NB * NE / 4 + 255) / 256, 256>>>(embed, enc_bias);
    ae_build_mask<<<1, 1024>>>(last_usage);

    dim3 gridA(NB / TBM, NF / TBN);
    ae_project<<<gridA, 128>>>(enc_W);
    dim3 gridB(NB / CBM, NF / CBN);
    ae_consensus<<<gridB, 256>>>(enc_W);

    size_t dynsm = (size_t)(NF + 2048) * sizeof(unsigned);
    cudaFuncSetAttribute(ae_select, cudaFuncAttributeMaxDynamicSharedMemorySize,
                         (int)dynsm);
    ae_select<<<NB, 256, dynsm>>>(0);
    ae_select<<<NB, 256, dynsm>>>(1);

    ae_recon_main<<<NB, 256>>>(lookup, enc_bias, out);
    ae_recon_dead<<<NB, 256>>>(lookup, out + (size_t)NB * NE);
}

// round 15
// speedup vs baseline: 2.4230x; 2.4230x over previous
#include <cuda_runtime.h>
#include <cstdint>

#define NB    4096      // batch rows
#define NE    1024      // embed dim
#define NF    32768     // features
#define KTOP  64
#define KDEAD 512
#define CUT_DEAD 50000
#define WIN   128u      // dead-boundary refinement window, in key ulps (7.5 sigma of chain noise)
#define CAND_CAP 256

// ================= scratch (static device globals; no allocations) =================
__device__ float    sc_proj[(size_t)NB * NF];     // chain fp32 projections (ref-family order)
__device__ float    sc_embm[(size_t)NB * NE];     // embed - bias
__device__ int      sc_tidx[NB * KTOP];
__device__ float    sc_twgt[NB * KTOP];
__device__ int      sc_didx[NB * KDEAD];
__device__ float    sc_dwgt[NB * KDEAD];
__device__ unsigned sc_mask[NF / 32];

typedef unsigned long long u64t;

__device__ __forceinline__ u64t pack_ff(float a, float b) {
    u64t r; asm("mov.b64 %0, {%1,%2};" : "=l"(r) : "f"(a), "f"(b)); return r;
}
__device__ __forceinline__ void unpack_ff(u64t v, float& lo, float& hi) {
    asm("mov.b64 {%0,%1}, %2;" : "=f"(lo), "=f"(hi) : "l"(v));
}
// packed dual fp32 FMA: each 32-bit half is an independent IEEE RN fma chain,
// so per output element this is a strictly ascending-k single-accumulator chain
// (bit-family of the reference GEMM — proven: output-0 rel_err 4.3e-7).
__device__ __forceinline__ void dfma(u64t& c, u64t a, u64t b) {
    asm("fma.rn.f32x2 %0, %1, %2, %0;" : "+l"(c) : "l"(a), "l"(b));
}

// ================= stage 1: embm = embed - bias =================
__global__ void ae_sub_bias(const float* __restrict__ embed,
                            const float* __restrict__ bias) {
    int i = blockIdx.x * blockDim.x + threadIdx.x;    // float4 index
    if (i < NB * NE / 4) {
        float4 e = ((const float4*)embed)[i];
        float4 b = ((const float4*)bias)[i & (NE / 4 - 1)];
        e.x -= b.x; e.y -= b.y; e.z -= b.z; e.w -= b.w;
        ((float4*)sc_embm)[i] = e;
    }
}

// ================= stage 2: dead mask (int32/int64 autodetect) =================
__global__ __launch_bounds__(1024)
void ae_build_mask(const int* __restrict__ lu) {
    __shared__ int s_hi_nonzero;
    const int t = threadIdx.x;
    if (t == 0) s_hi_nonzero = 0;
    __syncthreads();
    int nz = 0;
    for (int f = t; f < NF / 2; f += 1024) nz += (lu[2 * f + 1] != 0);
    if (nz) atomicAdd(&s_hi_nonzero, 1);
    __syncthreads();
    const bool is64 = (s_hi_nonzero == 0);
    unsigned m = 0;
    #pragma unroll
    for (int j = 0; j < 32; ++j) {
        int f = t * 32 + j;
        int v = is64 ? lu[2 * f] : lu[f];
        if (v > CUT_DEAD) m |= (1u << j);
    }
    sc_mask[t] = m;
}

// ================= stage 3: chain GEMM (proven, bitwise-preserved) =================
#define TBM 128
#define TBN 128
#define TBK 16
#define LDT 132

__global__ __launch_bounds__(128, 2)
void ae_project(const float* __restrict__ W) {
    __shared__ float sA[TBK * LDT];
    __shared__ float sB[TBK * LDT];

    const int t  = threadIdx.x;
    const int tn = t & 15;
    const int tm = t >> 4;
    const int m0 = blockIdx.x * TBM;
    const int n0 = blockIdx.y * TBN;

    const int lr = t >> 2;
    const int lc = (t & 3) * 4;

    const float* Ab = sc_embm + (size_t)(m0 + lr) * NE + lc;
    const float* Bb = W       + (size_t)(n0 + lr) * NE + lc;

    u64t acc[4][2][2][4];
    #pragma unroll
    for (int i = 0; i < 4; ++i)
        #pragma unroll
        for (int p = 0; p < 2; ++p)
            #pragma unroll
            for (int j = 0; j < 2; ++j)
                #pragma unroll
                for (int q = 0; q < 4; ++q) acc[i][p][j][q] = 0ull;

    float4 ra[4], rb[4];
    #pragma unroll
    for (int s = 0; s < 4; ++s) {
        ra[s] = *(const float4*)(Ab + (size_t)s * 32 * NE);
        rb[s] = *(const float4*)(Bb + (size_t)s * 32 * NE);
    }

    const int NSTEP = NE / TBK;     // 64
    for (int kt = 0; kt < NSTEP; ++kt) {
        #pragma unroll
        for (int s = 0; s < 4; ++s) {
            int r = lr + s * 32;
            sA[(lc + 0) * LDT + r] = ra[s].x;
            sA[(lc + 1) * LDT + r] = ra[s].y;
            sA[(lc + 2) * LDT + r] = ra[s].z;
            sA[(lc + 3) * LDT + r] = ra[s].w;
            sB[(lc + 0) * LDT + r] = rb[s].x;
            sB[(lc + 1) * LDT + r] = rb[s].y;
            sB[(lc + 2) * LDT + r] = rb[s].z;
            sB[(lc + 3) * LDT + r] = rb[s].w;
        }
        __syncthreads();

        if (kt + 1 < NSTEP) {
            const float* An = Ab + (kt + 1) * TBK;
            const float* Bn = Bb + (kt + 1) * TBK;
            #pragma unroll
            for (int s = 0; s < 4; ++s) {
                ra[s] = *(const float4*)(An + (size_t)s * 32 * NE);
                rb[s] = *(const float4*)(Bn + (size_t)s * 32 * NE);
            }
        }

        const float4* A4 = (const float4*)sA;
        const float4* B4 = (const float4*)sB;
        #pragma unroll
        for (int k = 0; k < TBK; ++k) {
            float4 av[4], bv[2];
            #pragma unroll
            for (int i = 0; i < 4; ++i) av[i] = A4[k * (LDT / 4) + tm + i * 8];
            bv[0] = B4[k * (LDT / 4) + tn];
            bv[1] = B4[k * (LDT / 4) + tn + 16];

            u64t am[4][2];
            #pragma unroll
            for (int i = 0; i < 4; ++i) {
                am[i][0] = pack_ff(av[i].x, av[i].y);
                am[i][1] = pack_ff(av[i].z, av[i].w);
            }
            u64t bd[2][4];
            #pragma unroll
            for (int j = 0; j < 2; ++j) {
                bd[j][0] = pack_ff(bv[j].x, bv[j].x);
                bd[j][1] = pack_ff(bv[j].y, bv[j].y);
                bd[j][2] = pack_ff(bv[j].z, bv[j].z);
                bd[j][3] = pack_ff(bv[j].w, bv[j].w);
            }
            #pragma unroll
            for (int i = 0; i < 4; ++i)
                #pragma unroll
                for (int p = 0; p < 2; ++p)
                    #pragma unroll
                    for (int j = 0; j < 2; ++j)
                        #pragma unroll
                        for (int q = 0; q < 4; ++q)
                            dfma(acc[i][p][j][q], am[i][p], bd[j][q]);
        }
        __syncthreads();
    }

    #pragma unroll
    for (int i = 0; i < 4; ++i)
        #pragma unroll
        for (int p = 0; p < 2; ++p) {
            float lo[8], hi[8];
            #pragma unroll
            for (int j = 0; j < 2; ++j)
                #pragma unroll
                for (int q = 0; q < 4; ++q)
                    unpack_ff(acc[i][p][j][q], lo[j * 4 + q], hi[j * 4 + q]);
            int mlo = m0 + tm * 4 + i * 32 + p * 2;
            float4* Cl = (float4*)(sc_proj + (size_t)mlo * NF + n0);
            float4* Ch = (float4*)(sc_proj + (size_t)(mlo + 1) * NF + n0);
            Cl[tn]      = make_float4(lo[0], lo[1], lo[2], lo[3]);
            Cl[tn + 16] = make_float4(lo[4], lo[5], lo[6], lo[7]);
            Ch[tn]      = make_float4(hi[0], hi[1], hi[2], hi[3]);
            Ch[tn + 16] = make_float4(hi[4], hi[5], hi[6], hi[7]);
        }
}

// ================= stage 4: fused selections =================
// Main top-64: chain keys, ties HIGH (proven R8).
// Dead top-512: chain-key radix threshold + fp64 exact re-rank of the
// +/-WIN-ulp boundary window (reproduces the proven exact ordering of R14).
__device__ __forceinline__ unsigned mono_key(float f) {
    unsigned u = __float_as_uint(f);
    return (u & 0x80000000u) ? ~u : (u | 0x80000000u);
}
__device__ __forceinline__ float inv_key(unsigned k) {
    unsigned u = (k & 0x80000000u) ? (k & 0x7FFFFFFFu) : ~k;
    return __uint_as_float(u);
}

struct SelCtl {
    unsigned prefix;
    unsigned above;
    unsigned need;
    unsigned thr;
    int eq_total;
};

// 3-level radix histogram -> exact fp32 threshold key (thr), above, need.
__device__ void radix_thresh(const unsigned* __restrict__ keys,
                             unsigned* __restrict__ hist,
                             const unsigned* __restrict__ s_m, bool masked,
                             int K, SelCtl* sv)
{
    const int tid = threadIdx.x;
    const int NT = 256;

    if (tid == 0) { sv->need = (unsigned)K; sv->above = 0; }
    __syncthreads();

    for (int b = tid; b < 2048; b += NT) hist[b] = 0;
    __syncthreads();
    for (int i = tid; i < NF; i += NT) {
        if (masked && !((s_m[i >> 5] >> (i & 31)) & 1u)) continue;
        atomicAdd(&hist[keys[i] >> 21], 1u);
    }
    __syncthreads();
    if (tid == 0) {
        unsigned need = sv->need, cum = 0; int sel = 0;
        for (int b = 2047; b >= 0; --b) {
            unsigned c = hist[b];
            if (cum + c >= need) { sel = b; break; }
            cum += c;
        }
        sv->above += cum; sv->need = need - cum; sv->prefix = (unsigned)sel;
    }
    __syncthreads();
    const unsigned p1 = sv->prefix;

    for (int b = tid; b < 2048; b += NT) hist[b] = 0;
    __syncthreads();
    for (int i = tid; i < NF; i += NT) {
        if (masked && !((s_m[i >> 5] >> (i & 31)) & 1u)) continue;
        unsigned k = keys[i];
        if ((k >> 21) != p1) continue;
        atomicAdd(&hist[(k >> 10) & 2047u], 1u);
    }
    __syncthreads();
    if (tid == 0) {
        unsigned need = sv->need, cum = 0; int sel = 0;
        for (int b = 2047; b >= 0; --b) {
            unsigned c = hist[b];
            if (cum + c >= need) { sel = b; break; }
            cum += c;
        }
        sv->above += cum; sv->need = need - cum;
        sv->prefix = (p1 << 11) | (unsigned)sel;
    }
    __syncthreads();
    const unsigned p2 = sv->prefix;

    for (int b = tid; b < 1024; b += NT) hist[b] = 0;
    __syncthreads();
    for (int i = tid; i < NF; i += NT) {
        if (masked && !((s_m[i >> 5] >> (i & 31)) & 1u)) continue;
        unsigned k = keys[i];
        if ((k >> 10) != p2) continue;
        atomicAdd(&hist[k & 1023u], 1u);
    }
    __syncthreads();
    if (tid == 0) {
        unsigned need = sv->need, cum = 0; int sel = 0;
        for (int b = 1023; b >= 0; --b) {
            unsigned c = hist[b];
            if (cum + c >= need) { sel = b; break; }
            cum += c;
        }
        sv->above += cum; sv->need = need - cum;
        sv->thr = (p2 << 10) | (unsigned)sel;
        sv->eq_total = 0;
    }
    __syncthreads();
}

__global__ __launch_bounds__(256)
void ae_select(const float* __restrict__ Wmat) {
    extern __shared__ unsigned dynsm[];
    unsigned* keys = dynsm;            // NF words
    unsigned* hist = dynsm + NF;       // 2048 words (reused as candidate idx list)
    __shared__ unsigned s_m[NF / 32];
    __shared__ SelCtl sv;
    __shared__ int s_gcnt[256], s_ecnt[256];
    __shared__ double s_cex[CAND_CAP];
    __shared__ unsigned char s_taken[CAND_CAP];
    __shared__ float s_embr[NE];
    __shared__ int s_nwritten;

    const int row = blockIdx.x;
    const int tid = threadIdx.x;
    const int NT = 256;
    const int wid = tid >> 5, lane = tid & 31;

    // load keys + mask + embm row
    const float4* p4 = (const float4*)(sc_proj + (size_t)row * NF);
    for (int i = tid; i < NF / 4; i += NT) {
        float4 v = p4[i];
        ((uint4*)keys)[i] = make_uint4(mono_key(v.x), mono_key(v.y),
                                       mono_key(v.z), mono_key(v.w));
    }
    for (int i = tid; i < NF / 32; i += NT) s_m[i] = sc_mask[i];
    for (int i = tid; i < NE; i += NT)
        s_embr[i] = sc_embm[(size_t)row * NE + i];
    __syncthreads();

    // ---------- PHASE 1: main top-64 (chain keys, ties HIGH; proven) ----------
    {
        radix_thresh(keys, hist, s_m, false, KTOP, &sv);
        const unsigned thr = sv.thr;
        const int above  = (int)sv.above;
        const int needEq = (int)sv.need;
        int* out_idx = sc_tidx + (size_t)row * KTOP;
        float* out_w = sc_twgt + (size_t)row * KTOP;

        const int CHUNK = NF / NT;
        const int base = tid * CHUNK;
        int cgt = 0, ceq = 0;
        for (int i = base; i < base + CHUNK; ++i) {
            unsigned k = keys[i];
            cgt += (k > thr);
            ceq += (k == thr);
        }
        s_gcnt[tid] = cgt; s_ecnt[tid] = ceq;
        __syncthreads();
        if (tid == 0) {
            int ag = 0, ae = 0;
            for (int j = 0; j < NT; ++j) {
                int g = s_gcnt[j], ec = s_ecnt[j];
                s_gcnt[j] = ag; s_ecnt[j] = ae;
                ag += g; ae += ec;
            }
            sv.eq_total = ae;
        }
        __syncthreads();
        const int eq_skip = sv.eq_total - needEq;   // ties HIGH
        int gpos = s_gcnt[tid], epos = s_ecnt[tid];
        for (int i = base; i < base + CHUNK; ++i) {
            unsigned k = keys[i];
            if (k > thr) {
                out_idx[gpos] = i; out_w[gpos] = inv_key(k); ++gpos;
            } else if (k == thr) {
                int slot = epos - eq_skip;
                if (slot >= 0 && slot < needEq) {
                    out_idx[above + slot] = i;
                    out_w[above + slot]   = inv_key(k);
                }
                ++epos;
            }
        }
        __syncthreads();
    }

    // ---------- PHASE 2: dead top-512 (masked) with exact boundary refinement ----------
    {
        radix_thresh(keys, hist, s_m, true, KDEAD, &sv);
        const unsigned T = sv.thr;
        const unsigned ThrHi = (T >= 0xFFFFFFFFu - WIN) ? 0xFFFFFFFFu : T + WIN;
        const unsigned ThrLo = (T <= WIN) ? 0u : T - WIN;
        int* out_idx = sc_didx + (size_t)row * KDEAD;
        float* out_w = sc_dwgt + (size_t)row * KDEAD;

        // count definite (key > ThrHi) and window (ThrLo..ThrHi) per chunk
        const int CHUNK = NF / NT;
        const int base = tid * CHUNK;
        int cdef = 0, cwin = 0;
        for (int i = base; i < base + CHUNK; ++i) {
            if (!((s_m[i >> 5] >> (i & 31)) & 1u)) continue;
            unsigned k = keys[i];
            if (k > ThrHi) ++cdef;
            else if (k >= ThrLo) ++cwin;
        }
        s_gcnt[tid] = cdef; s_ecnt[tid] = cwin;
        __syncthreads();
        __shared__ int s_nDef, s_nWin;
        if (tid == 0) {
            int ad = 0, aw = 0;
            for (int j = 0; j < NT; ++j) {
                int d = s_gcnt[j], w = s_ecnt[j];
                s_gcnt[j] = ad; s_ecnt[j] = aw;
                ad += d; aw += w;
            }
            s_nDef = ad;
            s_nWin = (aw > CAND_CAP) ? CAND_CAP : aw;
        }
        __syncthreads();
        const int nDef = s_nDef, nWin = s_nWin;

        // emit definite (ascending index); gather window candidates (ascending)
        int dpos = s_gcnt[tid], wpos = s_ecnt[tid];
        for (int i = base; i < base + CHUNK; ++i) {
            if (!((s_m[i >> 5] >> (i & 31)) & 1u)) continue;
            unsigned k = keys[i];
            if (k > ThrHi) {
                out_idx[dpos] = i; out_w[dpos] = inv_key(k); ++dpos;
            } else if (k >= ThrLo) {
                if (wpos < CAND_CAP) hist[wpos] = (unsigned)i;
                ++wpos;
            }
        }
        __syncthreads();

        // exact fp64 dot per candidate: one warp per candidate, fixed-order reduce
        for (int b = 0; b < (nWin + 7) / 8; ++b) {
            int c = b * 8 + wid;
            if (c < nWin) {
                const float* wr = Wmat + (size_t)hist[c] * NE;
                double p = 0.0;
                for (int j = lane; j < NE; j += 32)
                    p += (double)s_embr[j] * (double)wr[j];
                #pragma unroll
                for (int o = 16; o; o >>= 1)
                    p += __shfl_down_sync(0xFFFFFFFFu, p, o);
                if (lane == 0) s_cex[c] = p;
            }
        }
        for (int c = tid; c < nWin; c += NT) s_taken[c] = 0;
        __syncthreads();

        // thread 0: fill remaining slots by exact value desc (ties: higher index)
        if (tid == 0) {
            int slots = KDEAD - nDef;
            if (slots > nWin) slots = nWin;          // safety (cap overflow)
            int written = 0;
            for (int s = 0; s < slots; ++s) {
                int best = -1;
                double bex = 0.0; unsigned bidx = 0;
                for (int c = 0; c < nWin; ++c) {
                    if (s_taken[c]) continue;
                    double ex = s_cex[c]; unsigned ix = hist[c];
                    if (best < 0 || ex > bex || (ex == bex && ix > bidx)) {
                        best = c; bex = ex; bidx = ix;
                    }
                }
                s_taken[best] = 1;
                out_idx[nDef + s] = (int)bidx;
                out_w[nDef + s]   = (float)bex;      // RN(exact) weight
                ++written;
            }
            s_nwritten = nDef + written;
        }
        __syncthreads();
        // safety fill (unreachable in practice): keep outputs well-defined
        for (int s = s_nwritten + tid; s < KDEAD; s += NT) {
            out_idx[s] = 0; out_w[s] = 0.0f;
        }
    }
}

// ================= stage 5: reconstructions =================
__global__ __launch_bounds__(256)
void ae_recon_main(const float* __restrict__ lookup,
                   const float* __restrict__ bias,
                   float* __restrict__ out) {
    const int row = blockIdx.x;
    const int t = threadIdx.x;
    __shared__ int   si[KTOP];
    __shared__ float sw[KTOP];
    if (t < KTOP) {
        si[t] = sc_tidx[row * KTOP + t];
        sw[t] = sc_twgt[row * KTOP + t];
    }
    __syncthreads();
    float4 acc = ((const float4*)bias)[t];
    const float4* L4 = (const float4*)lookup;
    #pragma unroll 8
    for (int k = 0; k < KTOP; ++k) {
        float4 v = L4[(size_t)si[k] * (NE / 4) + t];
        float w = sw[k];
        acc.x = fmaf(w, v.x, acc.x);
        acc.y = fmaf(w, v.y, acc.y);
        acc.z = fmaf(w, v.z, acc.z);
        acc.w = fmaf(w, v.w, acc.w);
    }
    ((float4*)out)[(size_t)row * (NE / 4) + t] = acc;
}

__global__ __launch_bounds__(256)
void ae_recon_dead(const float* __restrict__ lookup,
                   float* __restrict__ out) {
    const int row = blockIdx.x;
    const int t = threadIdx.x;
    __shared__ int   si[KDEAD];
    __shared__ float sw[KDEAD];
    for (int k = t; k < KDEAD; k += 256) {
        si[k] = sc_didx[(size_t)row * KDEAD + k];
        sw[k] = sc_dwgt[(size_t)row * KDEAD + k];
    }
    __syncthreads();
    float4 acc = make_float4(0.f, 0.f, 0.f, 0.f);
    const float4* L4 = (const float4*)lookup;
    #pragma unroll 8
    for (int k = 0; k < KDEAD; ++k) {
        float4 v = L4[(size_t)si[k] * (NE / 4) + t];
        float w = sw[k];
        acc.x = fmaf(w, v.x, acc.x);
        acc.y = fmaf(w, v.y, acc.y);
        acc.z = fmaf(w, v.z, acc.z);
        acc.w = fmaf(w, v.w, acc.w);
    }
    ((float4*)out)[(size_t)row * (NE / 4) + t] = acc;
}

// ================= launcher =================
extern "C" void kernel_launch(void* const* d_in, const int* in_sizes, int n_in,
                              void* d_out, int out_size) {
    const float* embed      = (const float*)d_in[0];
    const float* enc_bias   = (const float*)d_in[1];
    const float* enc_W      = (const float*)d_in[2];
    const float* lookup     = (const float*)d_in[3];
    const int*   last_usage = (const int*)d_in[4];
    float* out = (float*)d_out;

    (void)in_sizes; (void)n_in; (void)out_size;

    ae_sub_bias<<<(NB * NE / 4 + 255) / 256, 256>>>(embed, enc_bias);
    ae_build_mask<<<1, 1024>>>(last_usage);

    dim3 gridA(NB / TBM, NF / TBN);
    ae_project<<<gridA, 128>>>(enc_W);

    size_t dynsm = (size_t)(NF + 2048) * sizeof(unsigned);
    cudaFuncSetAttribute(ae_select, cudaFuncAttributeMaxDynamicSharedMemorySize,
                         (int)dynsm);
    ae_select<<<NB, 256, dynsm>>>(enc_W);

    ae_recon_main<<<NB, 256>>>(lookup, enc_bias, out);
    ae_recon_dead<<<NB, 256>>>(lookup, out + (size_t)NB * NE);
}